// round 1
// baseline (speedup 1.0000x reference)
#include <cuda_runtime.h>
#include <cstdint>

#define N_NODES 50000
#define E_EDGES 800000
#define DIM 128      // input dim
#define ODIM 128     // output dim per relation

// Scratch: projected features for both relations, interleaved per node:
// g_x[n][0..127] = x1[n], g_x[n][128..255] = x2[n]
__device__ float g_x[(size_t)N_NODES * 256];

// ---------------------------------------------------------------------------
// GEMM: g_x[n][rel*128 + o] = sum_k inputs[n][k] * W_rel[k][o]
// BM=64 rows per block, BN=128 cols (= one full relation), blockIdx.y = rel.
// 256 threads; thread (m_idx = tid>>5, n_idx = tid&31) computes an 8x4 tile:
// rows row0 + m_idx*8 + r (r=0..7), cols 4*n_idx .. 4*n_idx+3.
// A is staged transposed in smem (padded stride 72 floats) so compute-side A
// loads are warp-broadcast LDS.128; B tile is float4 [k][n4], conflict-free.
// ---------------------------------------------------------------------------
#define GEMM_SMEM_BYTES (128 * 72 * 4 + 128 * 32 * 16)   // As + Bs = 100 KB

__global__ void __launch_bounds__(256) gemm_kernel(
    const float* __restrict__ A,
    const float* __restrict__ W1,
    const float* __restrict__ W2)
{
    extern __shared__ float smem[];
    float*  As  = smem;                       // [128][72] (k-major, padded)
    float4* Bs  = (float4*)(smem + 128 * 72); // [128][32] float4

    const float* W = (blockIdx.y == 0) ? W1 : W2;
    const int row0 = blockIdx.x * 64;
    const int tid  = threadIdx.x;

    // Load full 128x128 W tile (4096 float4), coalesced.
    const float4* W4 = (const float4*)W;
    #pragma unroll
    for (int i = 0; i < 16; i++) {
        int idx = tid + i * 256;
        Bs[idx] = W4[idx];
    }

    // Load 64x128 A tile, store transposed As[k][r].
    const float4* A4 = (const float4*)A;
    #pragma unroll
    for (int i = 0; i < 8; i++) {
        int idx = tid + i * 256;          // 0..2047
        int r   = idx >> 5;               // 0..63
        int c4  = idx & 31;               // 0..31
        float4 v = make_float4(0.f, 0.f, 0.f, 0.f);
        int grow = row0 + r;
        if (grow < N_NODES) v = A4[(size_t)grow * 32 + c4];
        int k = c4 * 4;
        As[(k + 0) * 72 + r] = v.x;
        As[(k + 1) * 72 + r] = v.y;
        As[(k + 2) * 72 + r] = v.z;
        As[(k + 3) * 72 + r] = v.w;
    }
    __syncthreads();

    const int n_idx = tid & 31;
    const int m_idx = tid >> 5;

    float4 acc[8];
    #pragma unroll
    for (int r = 0; r < 8; r++) acc[r] = make_float4(0.f, 0.f, 0.f, 0.f);

    const float4* As4 = (const float4*)As;  // stride 18 float4 per k row

    #pragma unroll 4
    for (int k = 0; k < 128; k++) {
        float4 b  = Bs[k * 32 + n_idx];
        float4 a0 = As4[k * 18 + m_idx * 2];      // rows m_idx*8 + 0..3 (broadcast)
        float4 a1 = As4[k * 18 + m_idx * 2 + 1];  // rows m_idx*8 + 4..7 (broadcast)
        float a_arr[8] = {a0.x, a0.y, a0.z, a0.w, a1.x, a1.y, a1.z, a1.w};
        #pragma unroll
        for (int r = 0; r < 8; r++) {
            acc[r].x += a_arr[r] * b.x;
            acc[r].y += a_arr[r] * b.y;
            acc[r].z += a_arr[r] * b.z;
            acc[r].w += a_arr[r] * b.w;
        }
    }

    // Store: g_x[row][rel*128 + 4*n_idx .. +3]
    float4* X4 = (float4*)g_x;                     // [N][64] float4
    const int col4 = blockIdx.y * 32 + n_idx;
    #pragma unroll
    for (int r = 0; r < 8; r++) {
        int grow = row0 + m_idx * 8 + r;
        if (grow < N_NODES) X4[(size_t)grow * 64 + col4] = acc[r];
    }
}

// ---------------------------------------------------------------------------
// Scatter: one warp per edge. Lane l handles 4 output features via one
// red.global.add.v4.f32 (16B vector atomic), cutting atomic op count 4x.
// ---------------------------------------------------------------------------
__global__ void __launch_bounds__(256) scatter_kernel(
    const int*   __restrict__ r1, const int* __restrict__ c1, const float* __restrict__ v1,
    const int*   __restrict__ r2, const int* __restrict__ c2, const float* __restrict__ v2,
    float* __restrict__ out)
{
    int w    = (blockIdx.x * blockDim.x + threadIdx.x) >> 5;
    int lane = threadIdx.x & 31;
    if (w >= 2 * E_EDGES) return;

    int rel, e;
    const int *rr, *cc;
    const float* vv;
    if (w < E_EDGES) { rel = 0; e = w;           rr = r1; cc = c1; vv = v1; }
    else             { rel = 1; e = w - E_EDGES; rr = r2; cc = c2; vv = v2; }

    const int   row = __ldg(rr + e);
    const int   col = __ldg(cc + e);
    const float val = __ldg(vv + e);

    const float4* X4 = (const float4*)g_x;
    float4 x = __ldg(X4 + (size_t)col * 64 + rel * 32 + lane);

    float* dst = out + (size_t)row * ODIM + lane * 4;
    asm volatile("red.global.add.v4.f32 [%0], {%1, %2, %3, %4};"
                 :: "l"(dst), "f"(x.x * val), "f"(x.y * val),
                    "f"(x.z * val), "f"(x.w * val)
                 : "memory");
}

// ---------------------------------------------------------------------------
// Zero-init and in-place ReLU (float4 grid-stride).
// ---------------------------------------------------------------------------
#define OUT_F4 ((size_t)N_NODES * ODIM / 4)   // 1,600,000

__global__ void zero_kernel(float4* __restrict__ out) {
    size_t i = (size_t)blockIdx.x * blockDim.x + threadIdx.x;
    if (i < OUT_F4) out[i] = make_float4(0.f, 0.f, 0.f, 0.f);
}

__global__ void relu_kernel(float4* __restrict__ out) {
    size_t i = (size_t)blockIdx.x * blockDim.x + threadIdx.x;
    if (i < OUT_F4) {
        float4 v = out[i];
        v.x = fmaxf(v.x, 0.f);
        v.y = fmaxf(v.y, 0.f);
        v.z = fmaxf(v.z, 0.f);
        v.w = fmaxf(v.w, 0.f);
        out[i] = v;
    }
}

// ---------------------------------------------------------------------------
extern "C" void kernel_launch(void* const* d_in, const int* in_sizes, int n_in,
                              void* d_out, int out_size)
{
    const float* inputs = (const float*)d_in[0];
    const int*   r1     = (const int*)  d_in[1];
    const int*   c1     = (const int*)  d_in[2];
    const float* v1     = (const float*)d_in[3];
    const int*   r2     = (const int*)  d_in[4];
    const int*   c2     = (const int*)  d_in[5];
    const float* v2     = (const float*)d_in[6];
    const float* W1     = (const float*)d_in[7];
    const float* W2     = (const float*)d_in[8];
    float*       out    = (float*)d_out;

    cudaFuncSetAttribute(gemm_kernel,
                         cudaFuncAttributeMaxDynamicSharedMemorySize,
                         GEMM_SMEM_BYTES);

    // 1) zero the accumulator (d_out is poisoned by the harness)
    {
        int blocks = (int)((OUT_F4 + 255) / 256);
        zero_kernel<<<blocks, 256>>>((float4*)out);
    }

    // 2) dense projection for both relations
    {
        dim3 grid((N_NODES + 63) / 64, 2);
        gemm_kernel<<<grid, 256, GEMM_SMEM_BYTES>>>(inputs, W1, W2);
    }

    // 3) edge scatter (both relations in one kernel), vector atomics
    {
        long total_warps = 2L * E_EDGES;
        int blocks = (int)((total_warps * 32 + 255) / 256);
        scatter_kernel<<<blocks, 256>>>(r1, c1, v1, r2, c2, v2, out);
    }

    // 4) ReLU in place
    {
        int blocks = (int)((OUT_F4 + 255) / 256);
        relu_kernel<<<blocks, 256>>>((float4*)out);
    }
}